// round 11
// baseline (speedup 1.0000x reference)
#include <cuda_runtime.h>

#define HN 1024
#define WN 1024
#define NN (HN*WN)
#define TPB 512
#define NBLK (NN/TPB)   // 2048
#define STEPS 50

#define SEGP 16
#define SEGL (NN/SEGP)      // 65536 elements per segment
#define WIN  1024           // speculation window: ulps each side of center
#define CAND (2*WIN)        // 2048 candidates per boundary
#define WPS  (CAND/32)      // 64 warps per speculated segment
#define SPEC_BLOCKS (1 + (SEGP-1)*WPS)   // 961

// ---- device-resident state (no allocations allowed) ----
__device__ float g_diag[NN], g_ce[NN], g_cw[NN], g_cs[NN], g_cn[NN];
__device__ float g_r[NN], g_pa[NN], g_pb[NN], g_Ap[NN], g_t[NN];
__device__ float g_rs, g_alpha, g_beta;
__device__ double g_segsum[SEGP];
__device__ float  g_seg0;                 // exact chain value after segment 0
__device__ float  g_tab[SEGP-1][CAND];    // speculative segment outputs

// ---- monotone fp32 <-> int order mapping (total order, ulp arithmetic) ----
__device__ __forceinline__ int f2o(float f) {
    int i = __float_as_int(f);
    return i < 0 ? (int)0x80000000 - i : i;
}
__device__ __forceinline__ float o2f(int o) {
    int i = o < 0 ? (int)0x80000000 - o : o;
    return __int_as_float(i);
}

// ---------------------------------------------------------------------------
// init: zero stencil planes, r = p = b, x = 0, t = rn(b*b)
// ---------------------------------------------------------------------------
__global__ void init_kernel(const float* __restrict__ b, float* __restrict__ x) {
    int i = blockIdx.x * TPB + threadIdx.x;
    g_diag[i] = 0.f; g_ce[i] = 0.f; g_cw[i] = 0.f; g_cs[i] = 0.f; g_cn[i] = 0.f;
    float bv = b[i];
    g_r[i] = bv; g_pa[i] = bv; x[i] = 0.f;
    g_t[i] = __fmul_rn(bv, bv);
}

// ---------------------------------------------------------------------------
// scatter COO -> 5 stencil planes (each nnz targets a unique slot; no races)
// ---------------------------------------------------------------------------
__global__ void scatter_kernel(const int* __restrict__ rows,
                               const int* __restrict__ cols,
                               const float* __restrict__ vals, int nnz) {
    int k = blockIdx.x * blockDim.x + threadIdx.x;
    if (k >= nnz) return;
    int r = rows[k], c = cols[k];
    float v = vals[k];
    int d = c - r;
    if (d == 0)        g_diag[r] = v;
    else if (d == 1)   g_ce[r]   = v;
    else if (d == -1)  g_cw[r]   = v;
    else if (d == WN)  g_cs[r]   = v;
    else               g_cn[r]   = v;   // d == -WN
}

// ---------------------------------------------------------------------------
// fp64 per-segment sums of g_t (parallel, deterministic tree; only needs to
// be accurate, not bit-matched to anything)
// ---------------------------------------------------------------------------
__global__ void segsum_kernel() {
    __shared__ double sh[1024];
    int seg = blockIdx.x;
    const float* __restrict__ t = g_t + seg * SEGL;
    double s = 0.0;
    for (int j = threadIdx.x; j < SEGL; j += 1024) s += (double)t[j];
    sh[threadIdx.x] = s;
    __syncthreads();
    for (int k = 512; k > 0; k >>= 1) {
        if (threadIdx.x < k) sh[threadIdx.x] += sh[threadIdx.x + k];
        __syncthreads();
    }
    if (threadIdx.x == 0) g_segsum[seg] = sh[0];
}

// ---------------------------------------------------------------------------
// Speculative segment chains. Block 0: exact chain of segment 0 from acc=0.
// Blocks 1..960: segment seg=1..15, each lane chains one candidate start
// value = center(seg) offset by [-WIN, WIN) ulps, where center = fp32 of the
// fp64 prefix sum. Chain arithmetic = strict rn(acc + t_k), ascending k --
// bit-identical to the reference's in-order scalar fp32 reduce.
// 16-deep float4 rotation hides L2 latency behind the 4-cyc FADD chain.
// ---------------------------------------------------------------------------
__global__ void __launch_bounds__(32, 1) spec_kernel() {
    int blk = blockIdx.x;
    int lane = threadIdx.x;
    int seg;
    float acc;
    if (blk == 0) {
        seg = 0;
        acc = 0.0f;
    } else {
        int b = blk - 1;
        seg = 1 + b / WPS;
        int w = b % WPS;
        double S = 0.0;
        for (int j = 0; j < seg; ++j) S += g_segsum[j];
        float center = (float)S;
        int d = w * 32 + lane - WIN;
        acc = o2f(f2o(center) + d);
    }

    const float4* __restrict__ t4 = (const float4*)(g_t + seg * SEGL);
    const int nchunk = SEGL / 4;    // 16384 float4 per segment

    float4 buf[16];
#pragma unroll
    for (int k = 0; k < 16; ++k) buf[k] = t4[k];

    for (int j = 0; j < nchunk; j += 16) {
#pragma unroll
        for (int k = 0; k < 16; ++k) {
            float4 v = buf[k];
            acc = __fadd_rn(acc, v.x);
            acc = __fadd_rn(acc, v.y);
            acc = __fadd_rn(acc, v.z);
            acc = __fadd_rn(acc, v.w);
            int nx = j + 16 + k;
            if (nx < nchunk) buf[k] = t4[nx];
        }
    }

    if (blk == 0) {
        if (lane == 0) g_seg0 = acc;
    } else {
        g_tab[seg - 1][(blk - 1) % WPS * 32 + lane] = acc;
    }
}

// ---------------------------------------------------------------------------
// Compose: walk boundaries selecting the table entry whose input EXACTLY
// equals the true incoming accumulator -> bit-identical to the serial chain.
// On window miss: exact serial fallback (rare). Then the scalar update.
// mode 0: rs = dot, beta = 0     mode 1: alpha = rs/dot
// mode 2: beta = dot/rs, rs = dot
// ---------------------------------------------------------------------------
__global__ void compose_kernel(int mode) {
    if (threadIdx.x != 0) return;
    float a = g_seg0;
    double S = g_segsum[0];
    bool miss = false;
    for (int i = 1; i < SEGP; ++i) {
        float center = (float)S;
        int d = f2o(a) - f2o(center);
        if (d < -WIN || d >= WIN) { miss = true; break; }
        a = g_tab[i - 1][d + WIN];
        S += g_segsum[i];
    }
    if (miss) {
        // exact serial fallback over the whole array (slow; expected never)
        float acc = 0.0f;
        for (int k = 0; k < NN; ++k) acc = __fadd_rn(acc, g_t[k]);
        a = acc;
    }
    if (mode == 0)      { g_rs = a; g_beta = 0.0f; }
    else if (mode == 1) { g_alpha = __fdiv_rn(g_rs, a); }
    else                { g_beta = __fdiv_rn(a, g_rs); g_rs = a; }
}

// ---------------------------------------------------------------------------
// fused: p_new = r + beta*p_old ; Ap = A*p_new ; t = rn(p_new*Ap)
// Element-wise arithmetic mirrors the reference bit-for-bit (no FMA; SpMV
// adds in row-sorted COO order: E, W, S, N, diag).
// flip selects p_old buffer (0: pa->pb, 1: pb->pa)
// ---------------------------------------------------------------------------
__device__ __forceinline__ float pnew_at(const float* __restrict__ pin,
                                         float beta, int j) {
    return __fadd_rn(g_r[j], __fmul_rn(beta, pin[j]));
}

__global__ void spmv_kernel(int flip) {
    const float* __restrict__ pin  = flip ? g_pb : g_pa;
    float*       __restrict__ pout = flip ? g_pa : g_pb;

    int i = blockIdx.x * TPB + threadIdx.x;
    float beta = g_beta;
    int xc = i & (WN - 1);

    float pn = pnew_at(pin, beta, i);

    float acc = 0.0f;
    if (xc < WN - 1) acc = __fadd_rn(acc, __fmul_rn(g_ce[i], pnew_at(pin, beta, i + 1)));
    if (xc > 0)      acc = __fadd_rn(acc, __fmul_rn(g_cw[i], pnew_at(pin, beta, i - 1)));
    if (i < NN - WN) acc = __fadd_rn(acc, __fmul_rn(g_cs[i], pnew_at(pin, beta, i + WN)));
    if (i >= WN)     acc = __fadd_rn(acc, __fmul_rn(g_cn[i], pnew_at(pin, beta, i - WN)));
    acc = __fadd_rn(acc, __fmul_rn(g_diag[i], pn));

    pout[i] = pn;
    g_Ap[i] = acc;
    g_t[i]  = __fmul_rn(pn, acc);
}

// ---------------------------------------------------------------------------
// fused: x += alpha*p ; r -= alpha*Ap ; t = rn(r*r)   (strict no-FMA)
// ---------------------------------------------------------------------------
__global__ void update_kernel(float* __restrict__ x, int flip) {
    const float* __restrict__ p = flip ? g_pa : g_pb;

    int i = blockIdx.x * TPB + threadIdx.x;
    float alpha = g_alpha;
    x[i] = __fadd_rn(x[i], __fmul_rn(alpha, p[i]));
    float rv = __fsub_rn(g_r[i], __fmul_rn(alpha, g_Ap[i]));
    g_r[i] = rv;
    g_t[i] = __fmul_rn(rv, rv);
}

// ---------------------------------------------------------------------------
static inline void launch_dot(int mode) {
    segsum_kernel<<<SEGP, 1024>>>();
    spec_kernel<<<SPEC_BLOCKS, 32>>>();
    compose_kernel<<<1, 32>>>(mode);
}

extern "C" void kernel_launch(void* const* d_in, const int* in_sizes, int n_in,
                              void* d_out, int out_size) {
    const int*   rows = (const int*)d_in[0];
    const int*   cols = (const int*)d_in[1];
    const float* vals = (const float*)d_in[2];
    const float* b    = (const float*)d_in[3];
    float*       x    = (float*)d_out;
    int nnz = in_sizes[0];

    init_kernel<<<NBLK, TPB>>>(b, x);
    scatter_kernel<<<(nnz + 255) / 256, 256>>>(rows, cols, vals, nnz);
    launch_dot(0);

    for (int it = 0; it < STEPS; ++it) {
        int flip = it & 1;
        spmv_kernel<<<NBLK, TPB>>>(flip);
        launch_dot(1);
        update_kernel<<<NBLK, TPB>>>(x, flip);
        launch_dot(2);
    }
}

// round 12
// speedup vs baseline: 5.7073x; 5.7073x over previous
#include <cuda_runtime.h>

#define HN 1024
#define WN 1024
#define NN (HN*WN)
#define TPB 512
#define NBLK (NN/TPB)   // 2048
#define STEPS 50

#define SEGP 16
#define SEGL (NN/SEGP)        // 65536 elements per segment
#define NBND (SEGP-1)         // 15 boundaries
#define CAND 2048             // candidates per boundary (both rounds)
#define WPB  (CAND/32)        // 64 warps per boundary
#define SPACE_A 64            // round-A candidate spacing (ulps)
#define HALF (CAND/2)         // 1024

// ---- device-resident state (no allocations allowed) ----
__device__ float g_diag[NN], g_ce[NN], g_cw[NN], g_cs[NN], g_cn[NN];
__device__ float g_r[NN], g_pa[NN], g_pb[NN], g_Ap[NN], g_t[NN];
__device__ float g_rs, g_alpha, g_beta;
__device__ double g_segsum[SEGP];
__device__ float  g_seg0;               // exact chain value after segment 0
__device__ float  g_tabA[NBND][CAND];   // round-A outputs (coarse)
__device__ float  g_tabB[NBND][CAND];   // round-B outputs (fine)
__device__ float  g_centerB[NBND];      // refined centers from compose-A

// ---- monotone fp32 <-> int order mapping (total order, ulp arithmetic) ----
__device__ __forceinline__ int f2o(float f) {
    int i = __float_as_int(f);
    return i < 0 ? (int)0x80000000 - i : i;
}
__device__ __forceinline__ float o2f(int o) {
    int i = o < 0 ? (int)0x80000000 - o : o;
    return __int_as_float(i);
}

// ---------------------------------------------------------------------------
// init: zero stencil planes, r = p = b, x = 0, t = rn(b*b)
// ---------------------------------------------------------------------------
__global__ void init_kernel(const float* __restrict__ b, float* __restrict__ x) {
    int i = blockIdx.x * TPB + threadIdx.x;
    g_diag[i] = 0.f; g_ce[i] = 0.f; g_cw[i] = 0.f; g_cs[i] = 0.f; g_cn[i] = 0.f;
    float bv = b[i];
    g_r[i] = bv; g_pa[i] = bv; x[i] = 0.f;
    g_t[i] = __fmul_rn(bv, bv);
}

__global__ void scatter_kernel(const int* __restrict__ rows,
                               const int* __restrict__ cols,
                               const float* __restrict__ vals, int nnz) {
    int k = blockIdx.x * blockDim.x + threadIdx.x;
    if (k >= nnz) return;
    int r = rows[k], c = cols[k];
    float v = vals[k];
    int d = c - r;
    if (d == 0)        g_diag[r] = v;
    else if (d == 1)   g_ce[r]   = v;
    else if (d == -1)  g_cw[r]   = v;
    else if (d == WN)  g_cs[r]   = v;
    else               g_cn[r]   = v;   // d == -WN
}

// ---------------------------------------------------------------------------
// fp64 per-segment sums of g_t (parallel, deterministic tree)
// ---------------------------------------------------------------------------
__global__ void segsum_kernel() {
    __shared__ double sh[1024];
    int seg = blockIdx.x;
    const float* __restrict__ t = g_t + seg * SEGL;
    double s = 0.0;
    for (int j = threadIdx.x; j < SEGL; j += 1024) s += (double)t[j];
    sh[threadIdx.x] = s;
    __syncthreads();
    for (int k = 512; k > 0; k >>= 1) {
        if (threadIdx.x < k) sh[threadIdx.x] += sh[threadIdx.x + k];
        __syncthreads();
    }
    if (threadIdx.x == 0) g_segsum[seg] = sh[0];
}

// ---------------------------------------------------------------------------
// Segment chain: strict rn(acc + t_k), ascending k — bit-identical to the
// reference's in-order scalar fp32 reduce. 16-deep float4 rotation keeps
// ~1024 cycles of independent-load lead over the 4-cyc FADD chain.
// ---------------------------------------------------------------------------
__device__ __forceinline__ float chain_segment(int seg, float acc) {
    const float4* __restrict__ t4 = (const float4*)(g_t + seg * SEGL);
    const int nchunk = SEGL / 4;    // 16384

    float4 buf[16];
#pragma unroll
    for (int k = 0; k < 16; ++k) buf[k] = t4[k];

    for (int j = 0; j < nchunk; j += 16) {
#pragma unroll
        for (int k = 0; k < 16; ++k) {
            float4 v = buf[k];
            acc = __fadd_rn(acc, v.x);
            acc = __fadd_rn(acc, v.y);
            acc = __fadd_rn(acc, v.z);
            acc = __fadd_rn(acc, v.w);
            int nx = j + 16 + k;
            if (nx < nchunk) buf[k] = t4[nx];
        }
    }
    return acc;
}

// ---------------------------------------------------------------------------
// Round A: coarse speculation. Block 0 = exact segment-0 chain from 0.
// Blocks 1..960: boundary seg = 1..15, candidates at SPACE_A-ulp spacing
// around fp32(fp64 prefix sum), spanning +-65536 ulps.
// ---------------------------------------------------------------------------
__global__ void __launch_bounds__(32, 1) specA_kernel() {
    int blk = blockIdx.x;
    int lane = threadIdx.x;
    if (blk == 0) {
        float acc = chain_segment(0, 0.0f);
        if (lane == 0) g_seg0 = acc;
        return;
    }
    int b = blk - 1;
    int seg = 1 + b / WPB;
    int w = b % WPB;
    double S = 0.0;
    for (int j = 0; j < seg; ++j) S += g_segsum[j];
    float center = (float)S;
    int ci = w * 32 + lane;
    float start = o2f(f2o(center) + (ci - HALF) * SPACE_A);
    g_tabA[seg - 1][ci] = chain_segment(seg, start);
}

// ---------------------------------------------------------------------------
// Compose A: walk boundaries with nearest-candidate lookups; write the
// refined per-boundary centers for round B. centerB[i-1] = approx incoming
// accumulator at boundary i (exact at boundary 1).
// ---------------------------------------------------------------------------
__global__ void composeA_kernel() {
    if (threadIdx.x != 0) return;
    float a = g_seg0;
    double S = g_segsum[0];
    for (int i = 1; i < SEGP; ++i) {
        g_centerB[i - 1] = a;
        float centerA = (float)S;
        int d = f2o(a) - f2o(centerA);
        int ci = (d + HALF * SPACE_A + SPACE_A / 2) >> 6;   // nearest, SPACE_A=64
        if (ci < 0) ci = 0;
        if (ci > CAND - 1) ci = CAND - 1;
        a = g_tabA[i - 1][ci];
        S += g_segsum[i];
    }
}

// ---------------------------------------------------------------------------
// Round B: fine speculation. 960 blocks: boundary seg = 1..15, candidates at
// 1-ulp spacing around centerB (true accumulator guaranteed inside).
// ---------------------------------------------------------------------------
__global__ void __launch_bounds__(32, 1) specB_kernel() {
    int b = blockIdx.x;
    int lane = threadIdx.x;
    int seg = 1 + b / WPB;
    int w = b % WPB;
    float center = g_centerB[seg - 1];
    int ci = w * 32 + lane;
    float start = o2f(f2o(center) + ci - HALF);
    g_tabB[seg - 1][ci] = chain_segment(seg, start);
}

// ---------------------------------------------------------------------------
// Compose B: exact walk — select by bit-equality of the incoming accumulator.
// Result is bit-identical to the full serial chain. Serial fallback kept for
// the (expected-never) miss case. Then the scalar update.
// mode 0: rs = dot, beta = 0   mode 1: alpha = rs/dot
// mode 2: beta = dot/rs, rs = dot
// ---------------------------------------------------------------------------
__global__ void composeB_kernel(int mode) {
    if (threadIdx.x != 0) return;
    float a = g_seg0;
    bool miss = false;
    for (int i = 1; i < SEGP; ++i) {
        int d = f2o(a) - f2o(g_centerB[i - 1]);
        if (d < -HALF || d >= HALF) { miss = true; break; }
        a = g_tabB[i - 1][d + HALF];
    }
    if (miss) {
        const float4* __restrict__ t4 = (const float4*)g_t;
        float acc = 0.0f;
        for (int j = 0; j < NN / 4; j += 8) {
            float4 v0 = t4[j+0], v1 = t4[j+1], v2 = t4[j+2], v3 = t4[j+3];
            float4 v4 = t4[j+4], v5 = t4[j+5], v6 = t4[j+6], v7 = t4[j+7];
            acc=__fadd_rn(acc,v0.x); acc=__fadd_rn(acc,v0.y); acc=__fadd_rn(acc,v0.z); acc=__fadd_rn(acc,v0.w);
            acc=__fadd_rn(acc,v1.x); acc=__fadd_rn(acc,v1.y); acc=__fadd_rn(acc,v1.z); acc=__fadd_rn(acc,v1.w);
            acc=__fadd_rn(acc,v2.x); acc=__fadd_rn(acc,v2.y); acc=__fadd_rn(acc,v2.z); acc=__fadd_rn(acc,v2.w);
            acc=__fadd_rn(acc,v3.x); acc=__fadd_rn(acc,v3.y); acc=__fadd_rn(acc,v3.z); acc=__fadd_rn(acc,v3.w);
            acc=__fadd_rn(acc,v4.x); acc=__fadd_rn(acc,v4.y); acc=__fadd_rn(acc,v4.z); acc=__fadd_rn(acc,v4.w);
            acc=__fadd_rn(acc,v5.x); acc=__fadd_rn(acc,v5.y); acc=__fadd_rn(acc,v5.z); acc=__fadd_rn(acc,v5.w);
            acc=__fadd_rn(acc,v6.x); acc=__fadd_rn(acc,v6.y); acc=__fadd_rn(acc,v6.z); acc=__fadd_rn(acc,v6.w);
            acc=__fadd_rn(acc,v7.x); acc=__fadd_rn(acc,v7.y); acc=__fadd_rn(acc,v7.z); acc=__fadd_rn(acc,v7.w);
        }
        a = acc;
    }
    if (mode == 0)      { g_rs = a; g_beta = 0.0f; }
    else if (mode == 1) { g_alpha = __fdiv_rn(g_rs, a); }
    else                { g_beta = __fdiv_rn(a, g_rs); g_rs = a; }
}

// ---------------------------------------------------------------------------
// fused: p_new = r + beta*p_old ; Ap = A*p_new ; t = rn(p_new*Ap)
// Element-wise arithmetic mirrors the reference bit-for-bit (no FMA; SpMV
// adds in row-sorted COO order: E, W, S, N, diag).
// ---------------------------------------------------------------------------
__device__ __forceinline__ float pnew_at(const float* __restrict__ pin,
                                         float beta, int j) {
    return __fadd_rn(g_r[j], __fmul_rn(beta, pin[j]));
}

__global__ void spmv_kernel(int flip) {
    const float* __restrict__ pin  = flip ? g_pb : g_pa;
    float*       __restrict__ pout = flip ? g_pa : g_pb;

    int i = blockIdx.x * TPB + threadIdx.x;
    float beta = g_beta;
    int xc = i & (WN - 1);

    float pn = pnew_at(pin, beta, i);

    float acc = 0.0f;
    if (xc < WN - 1) acc = __fadd_rn(acc, __fmul_rn(g_ce[i], pnew_at(pin, beta, i + 1)));
    if (xc > 0)      acc = __fadd_rn(acc, __fmul_rn(g_cw[i], pnew_at(pin, beta, i - 1)));
    if (i < NN - WN) acc = __fadd_rn(acc, __fmul_rn(g_cs[i], pnew_at(pin, beta, i + WN)));
    if (i >= WN)     acc = __fadd_rn(acc, __fmul_rn(g_cn[i], pnew_at(pin, beta, i - WN)));
    acc = __fadd_rn(acc, __fmul_rn(g_diag[i], pn));

    pout[i] = pn;
    g_Ap[i] = acc;
    g_t[i]  = __fmul_rn(pn, acc);
}

// ---------------------------------------------------------------------------
// fused: x += alpha*p ; r -= alpha*Ap ; t = rn(r*r)   (strict no-FMA)
// ---------------------------------------------------------------------------
__global__ void update_kernel(float* __restrict__ x, int flip) {
    const float* __restrict__ p = flip ? g_pa : g_pb;

    int i = blockIdx.x * TPB + threadIdx.x;
    float alpha = g_alpha;
    x[i] = __fadd_rn(x[i], __fmul_rn(alpha, p[i]));
    float rv = __fsub_rn(g_r[i], __fmul_rn(alpha, g_Ap[i]));
    g_r[i] = rv;
    g_t[i] = __fmul_rn(rv, rv);
}

// ---------------------------------------------------------------------------
static inline void launch_dot(int mode) {
    segsum_kernel<<<SEGP, 1024>>>();
    specA_kernel<<<1 + NBND * WPB, 32>>>();
    composeA_kernel<<<1, 32>>>();
    specB_kernel<<<NBND * WPB, 32>>>();
    composeB_kernel<<<1, 32>>>(mode);
}

extern "C" void kernel_launch(void* const* d_in, const int* in_sizes, int n_in,
                              void* d_out, int out_size) {
    const int*   rows = (const int*)d_in[0];
    const int*   cols = (const int*)d_in[1];
    const float* vals = (const float*)d_in[2];
    const float* b    = (const float*)d_in[3];
    float*       x    = (float*)d_out;
    int nnz = in_sizes[0];

    init_kernel<<<NBLK, TPB>>>(b, x);
    scatter_kernel<<<(nnz + 255) / 256, 256>>>(rows, cols, vals, nnz);
    launch_dot(0);

    for (int it = 0; it < STEPS; ++it) {
        int flip = it & 1;
        spmv_kernel<<<NBLK, TPB>>>(flip);
        launch_dot(1);
        update_kernel<<<NBLK, TPB>>>(x, flip);
        launch_dot(2);
    }
}

// round 14
// speedup vs baseline: 18.4796x; 3.2379x over previous
#include <cuda_runtime.h>
#include <cstdint>

#define HN 1024
#define WN 1024
#define NN (HN*WN)
#define TPB 512
#define NBLK (NN/TPB)   // 2048
#define STEPS 50

#define SEGP 32
#define SEGL (NN/SEGP)        // 32768 elements per segment
#define NBND (SEGP-1)         // 31 boundaries
#define CAND 2048             // candidates per boundary (both rounds)
#define WPB  (CAND/32)        // 64 warps per boundary
#define SPACE_A 32            // round-A candidate spacing (ulps)
#define HALF (CAND/2)         // 1024
#define BPSEG 64              // sweep blocks per segment (NBLK/SEGP)

#define STAGE_F 512           // floats per smem stage (2KB)
#define NSTAGE 4
#define NTILE (SEGL/STAGE_F)  // 64 tiles per segment

// ---- device-resident state (no allocations allowed) ----
__device__ float g_diag[NN], g_ce[NN], g_cw[NN], g_cs[NN], g_cn[NN];
__device__ float g_r[NN], g_pa[NN], g_pb[NN], g_Ap[NN], g_t[NN];
__device__ float g_rs, g_alpha, g_beta;
__device__ double g_part[NBLK];         // per-sweep-block fp64 partials of t
__device__ double g_pref[SEGP];         // exclusive fp64 prefix per segment
__device__ float  g_seg0;               // exact chain value after segment 0
__device__ float  g_tabA[NBND][CAND];   // round-A outputs (coarse)
__device__ float  g_tabB[NBND][CAND];   // round-B outputs (fine)
__device__ float  g_centerB[NBND];      // refined centers from compose-A

// ---- monotone fp32 <-> int order mapping (total order, ulp arithmetic) ----
__device__ __forceinline__ int f2o(float f) {
    int i = __float_as_int(f);
    return i < 0 ? (int)0x80000000 - i : i;
}
__device__ __forceinline__ float o2f(int o) {
    int i = o < 0 ? (int)0x80000000 - o : o;
    return __int_as_float(i);
}

// ---- cp.async helpers ----
__device__ __forceinline__ void cp_async16(uint32_t sdst, const void* gsrc) {
    asm volatile("cp.async.cg.shared.global [%0], [%1], 16;\n" :: "r"(sdst), "l"(gsrc));
}
__device__ __forceinline__ void cp_commit() {
    asm volatile("cp.async.commit_group;\n" ::: "memory");
}
template <int N> __device__ __forceinline__ void cp_wait() {
    asm volatile("cp.async.wait_group %0;\n" :: "n"(N) : "memory");
}

// ---------------------------------------------------------------------------
// per-block fp64 partial of g_t over this block's 512 elements
// ---------------------------------------------------------------------------
__device__ __forceinline__ void block_partial(float tv) {
    __shared__ double sh[TPB];
    sh[threadIdx.x] = (double)tv;
    __syncthreads();
    for (int s = TPB / 2; s > 0; s >>= 1) {
        if (threadIdx.x < s) sh[threadIdx.x] += sh[threadIdx.x + s];
        __syncthreads();
    }
    if (threadIdx.x == 0) g_part[blockIdx.x] = sh[0];
}

// ---------------------------------------------------------------------------
// init: zero stencil planes, r = p = b, x = 0, t = rn(b*b), block partials
// ---------------------------------------------------------------------------
__global__ void init_kernel(const float* __restrict__ b, float* __restrict__ x) {
    int i = blockIdx.x * TPB + threadIdx.x;
    g_diag[i] = 0.f; g_ce[i] = 0.f; g_cw[i] = 0.f; g_cs[i] = 0.f; g_cn[i] = 0.f;
    float bv = b[i];
    g_r[i] = bv; g_pa[i] = bv; x[i] = 0.f;
    float tv = __fmul_rn(bv, bv);
    g_t[i] = tv;
    block_partial(tv);
}

__global__ void scatter_kernel(const int* __restrict__ rows,
                               const int* __restrict__ cols,
                               const float* __restrict__ vals, int nnz) {
    int k = blockIdx.x * blockDim.x + threadIdx.x;
    if (k >= nnz) return;
    int r = rows[k], c = cols[k];
    float v = vals[k];
    int d = c - r;
    if (d == 0)        g_diag[r] = v;
    else if (d == 1)   g_ce[r]   = v;
    else if (d == -1)  g_cw[r]   = v;
    else if (d == WN)  g_cs[r]   = v;
    else               g_cn[r]   = v;   // d == -WN
}

// ---------------------------------------------------------------------------
// prefix: lane s sums its segment's 64 block-partials, warp-scan -> g_pref
// (exclusive prefix: sum of segments < s)
// ---------------------------------------------------------------------------
__global__ void prefix_kernel() {
    int lane = threadIdx.x;   // 0..31 = segment id
    double s = 0.0;
    const double* p = g_part + lane * BPSEG;
    for (int j = 0; j < BPSEG; ++j) s += p[j];
    // inclusive scan
    double inc = s;
    for (int d = 1; d < 32; d <<= 1) {
        double v = __shfl_up_sync(0xFFFFFFFFu, inc, d);
        if (lane >= d) inc += v;
    }
    g_pref[lane] = inc - s;   // exclusive
}

// ---------------------------------------------------------------------------
// Segment chain via cp.async smem staging. Strict rn(acc + t_k), ascending k
// -- bit-identical to the reference's in-order scalar fp32 reduce.
// All 32 lanes chain the same data (broadcast LDS) with their own acc.
// 4-stage 2KB ring; wait distance 2 => ~3 tiles (6KB, ~6000 cyc) of lead.
// ---------------------------------------------------------------------------
__device__ float chain_segment(int seg, float acc, float* sbuf, int lane) {
    const char* gbase = (const char*)(g_t + seg * SEGL);
    uint32_t sbase = (uint32_t)__cvta_generic_to_shared(sbuf);

    // prologue: stages 0..NSTAGE-2 = tiles 0..2
#pragma unroll
    for (int t = 0; t < NSTAGE - 1; ++t) {
#pragma unroll
        for (int q = 0; q < 4; ++q)
            cp_async16(sbase + t * 2048 + q * 512 + lane * 16,
                       gbase + t * 2048 + q * 512 + lane * 16);
        cp_commit();
    }

    for (int t = 0; t < NTILE; ++t) {
        cp_wait<NSTAGE - 2>();
        __syncwarp();
        const float4* s4 = (const float4*)(sbuf + (t % NSTAGE) * STAGE_F);
#pragma unroll 8
        for (int k = 0; k < STAGE_F / 4; ++k) {
            float4 v = s4[k];
            acc = __fadd_rn(acc, v.x);
            acc = __fadd_rn(acc, v.y);
            acc = __fadd_rn(acc, v.z);
            acc = __fadd_rn(acc, v.w);
        }
        __syncwarp();
        int ft = t + NSTAGE - 1;
        if (ft < NTILE) {
            uint32_t sdst = sbase + (ft % NSTAGE) * 2048;
            const char* gsrc = gbase + ft * 2048;
#pragma unroll
            for (int q = 0; q < 4; ++q)
                cp_async16(sdst + q * 512 + lane * 16, gsrc + q * 512 + lane * 16);
        }
        cp_commit();   // one group per iteration keeps wait accounting fixed
    }
    return acc;
}

// ---------------------------------------------------------------------------
// Round A: coarse speculation. Block 0 = exact segment-0 chain from 0.
// Blocks 1..: boundary seg = 1..31, candidates at SPACE_A-ulp spacing around
// fp32(fp64 prefix), spanning +-32768 ulps.
// ---------------------------------------------------------------------------
__global__ void __launch_bounds__(32, 1) specA_kernel() {
    __shared__ __align__(16) float sbuf[NSTAGE * STAGE_F];
    int blk = blockIdx.x;
    int lane = threadIdx.x;
    if (blk == 0) {
        float acc = chain_segment(0, 0.0f, sbuf, lane);
        if (lane == 0) g_seg0 = acc;
        return;
    }
    int b = blk - 1;
    int seg = 1 + b / WPB;
    int w = b % WPB;
    float center = (float)g_pref[seg];
    int ci = w * 32 + lane;
    float start = o2f(f2o(center) + (ci - HALF) * SPACE_A);
    g_tabA[seg - 1][ci] = chain_segment(seg, start, sbuf, lane);
}

// ---------------------------------------------------------------------------
// Compose A: nearest-candidate walk; writes refined per-boundary centers.
// ---------------------------------------------------------------------------
__global__ void composeA_kernel() {
    if (threadIdx.x != 0) return;
    float a = g_seg0;
    for (int i = 1; i < SEGP; ++i) {
        g_centerB[i - 1] = a;
        float centerA = (float)g_pref[i];
        int d = f2o(a) - f2o(centerA);
        int ci = (d + HALF * SPACE_A + SPACE_A / 2) >> 5;   // nearest, SPACE_A=32
        if (ci < 0) ci = 0;
        if (ci > CAND - 1) ci = CAND - 1;
        a = g_tabA[i - 1][ci];
    }
}

// ---------------------------------------------------------------------------
// Round B: fine speculation at 1-ulp spacing around centerB.
// ---------------------------------------------------------------------------
__global__ void __launch_bounds__(32, 1) specB_kernel() {
    __shared__ __align__(16) float sbuf[NSTAGE * STAGE_F];
    int b = blockIdx.x;
    int lane = threadIdx.x;
    int seg = 1 + b / WPB;
    int w = b % WPB;
    float center = g_centerB[seg - 1];
    int ci = w * 32 + lane;
    float start = o2f(f2o(center) + ci - HALF);
    g_tabB[seg - 1][ci] = chain_segment(seg, start, sbuf, lane);
}

// ---------------------------------------------------------------------------
// Compose B: exact bit-equality walk -> bit-identical to the serial chain.
// Serial fallback kept for the (expected-never) miss case.
// mode 0: rs = dot, beta = 0   mode 1: alpha = rs/dot
// mode 2: beta = dot/rs, rs = dot
// ---------------------------------------------------------------------------
__global__ void composeB_kernel(int mode) {
    if (threadIdx.x != 0) return;
    float a = g_seg0;
    bool miss = false;
    for (int i = 1; i < SEGP; ++i) {
        int d = f2o(a) - f2o(g_centerB[i - 1]);
        if (d < -HALF || d >= HALF) { miss = true; break; }
        a = g_tabB[i - 1][d + HALF];
    }
    if (miss) {
        const float4* __restrict__ t4 = (const float4*)g_t;
        float acc = 0.0f;
        for (int j = 0; j < NN / 4; j += 8) {
            float4 v0 = t4[j+0], v1 = t4[j+1], v2 = t4[j+2], v3 = t4[j+3];
            float4 v4 = t4[j+4], v5 = t4[j+5], v6 = t4[j+6], v7 = t4[j+7];
            acc=__fadd_rn(acc,v0.x); acc=__fadd_rn(acc,v0.y); acc=__fadd_rn(acc,v0.z); acc=__fadd_rn(acc,v0.w);
            acc=__fadd_rn(acc,v1.x); acc=__fadd_rn(acc,v1.y); acc=__fadd_rn(acc,v1.z); acc=__fadd_rn(acc,v1.w);
            acc=__fadd_rn(acc,v2.x); acc=__fadd_rn(acc,v2.y); acc=__fadd_rn(acc,v2.z); acc=__fadd_rn(acc,v2.w);
            acc=__fadd_rn(acc,v3.x); acc=__fadd_rn(acc,v3.y); acc=__fadd_rn(acc,v3.z); acc=__fadd_rn(acc,v3.w);
            acc=__fadd_rn(acc,v4.x); acc=__fadd_rn(acc,v4.y); acc=__fadd_rn(acc,v4.z); acc=__fadd_rn(acc,v4.w);
            acc=__fadd_rn(acc,v5.x); acc=__fadd_rn(acc,v5.y); acc=__fadd_rn(acc,v5.z); acc=__fadd_rn(acc,v5.w);
            acc=__fadd_rn(acc,v6.x); acc=__fadd_rn(acc,v6.y); acc=__fadd_rn(acc,v6.z); acc=__fadd_rn(acc,v6.w);
            acc=__fadd_rn(acc,v7.x); acc=__fadd_rn(acc,v7.y); acc=__fadd_rn(acc,v7.z); acc=__fadd_rn(acc,v7.w);
        }
        a = acc;
    }
    if (mode == 0)      { g_rs = a; g_beta = 0.0f; }
    else if (mode == 1) { g_alpha = __fdiv_rn(g_rs, a); }
    else                { g_beta = __fdiv_rn(a, g_rs); g_rs = a; }
}

// ---------------------------------------------------------------------------
// fused: p_new = r + beta*p_old ; Ap = A*p_new ; t = rn(p_new*Ap) ; partials
// Element-wise arithmetic mirrors the reference bit-for-bit (no FMA; SpMV
// adds in row-sorted COO order: E, W, S, N, diag).
// ---------------------------------------------------------------------------
__device__ __forceinline__ float pnew_at(const float* __restrict__ pin,
                                         float beta, int j) {
    return __fadd_rn(g_r[j], __fmul_rn(beta, pin[j]));
}

__global__ void spmv_kernel(int flip) {
    const float* __restrict__ pin  = flip ? g_pb : g_pa;
    float*       __restrict__ pout = flip ? g_pa : g_pb;

    int i = blockIdx.x * TPB + threadIdx.x;
    float beta = g_beta;
    int xc = i & (WN - 1);

    float pn = pnew_at(pin, beta, i);

    float acc = 0.0f;
    if (xc < WN - 1) acc = __fadd_rn(acc, __fmul_rn(g_ce[i], pnew_at(pin, beta, i + 1)));
    if (xc > 0)      acc = __fadd_rn(acc, __fmul_rn(g_cw[i], pnew_at(pin, beta, i - 1)));
    if (i < NN - WN) acc = __fadd_rn(acc, __fmul_rn(g_cs[i], pnew_at(pin, beta, i + WN)));
    if (i >= WN)     acc = __fadd_rn(acc, __fmul_rn(g_cn[i], pnew_at(pin, beta, i - WN)));
    acc = __fadd_rn(acc, __fmul_rn(g_diag[i], pn));

    pout[i] = pn;
    g_Ap[i] = acc;
    float tv = __fmul_rn(pn, acc);
    g_t[i] = tv;
    block_partial(tv);
}

// ---------------------------------------------------------------------------
// fused: x += alpha*p ; r -= alpha*Ap ; t = rn(r*r) ; partials  (no FMA)
// ---------------------------------------------------------------------------
__global__ void update_kernel(float* __restrict__ x, int flip) {
    const float* __restrict__ p = flip ? g_pa : g_pb;

    int i = blockIdx.x * TPB + threadIdx.x;
    float alpha = g_alpha;
    x[i] = __fadd_rn(x[i], __fmul_rn(alpha, p[i]));
    float rv = __fsub_rn(g_r[i], __fmul_rn(alpha, g_Ap[i]));
    g_r[i] = rv;
    float tv = __fmul_rn(rv, rv);
    g_t[i] = tv;
    block_partial(tv);
}

// ---------------------------------------------------------------------------
static inline void launch_dot(int mode) {
    prefix_kernel<<<1, 32>>>();
    specA_kernel<<<1 + NBND * WPB, 32>>>();
    composeA_kernel<<<1, 32>>>();
    specB_kernel<<<NBND * WPB, 32>>>();
    composeB_kernel<<<1, 32>>>(mode);
}

extern "C" void kernel_launch(void* const* d_in, const int* in_sizes, int n_in,
                              void* d_out, int out_size) {
    const int*   rows = (const int*)d_in[0];
    const int*   cols = (const int*)d_in[1];
    const float* vals = (const float*)d_in[2];
    const float* b    = (const float*)d_in[3];
    float*       x    = (float*)d_out;
    int nnz = in_sizes[0];

    init_kernel<<<NBLK, TPB>>>(b, x);
    scatter_kernel<<<(nnz + 255) / 256, 256>>>(rows, cols, vals, nnz);
    launch_dot(0);

    for (int it = 0; it < STEPS; ++it) {
        int flip = it & 1;
        spmv_kernel<<<NBLK, TPB>>>(flip);
        launch_dot(1);
        update_kernel<<<NBLK, TPB>>>(x, flip);
        launch_dot(2);
    }
}

// round 15
// speedup vs baseline: 23.6998x; 1.2825x over previous
#include <cuda_runtime.h>
#include <cstdint>

#define HN 1024
#define WN 1024
#define NN (HN*WN)
#define TPB 512
#define NBLK (NN/TPB)   // 2048
#define STEPS 50

#define SEGP 32
#define SEGL (NN/SEGP)        // 32768 elements per segment
#define NBND (SEGP-1)         // 31 boundaries
#define CAND 2048             // candidates per boundary (both rounds)
#define CPL  4                // candidates per lane (2 x f32x2 chains)
#define WPB  (CAND/(32*CPL))  // 16 warps per boundary
#define SPACE_A 32            // round-A candidate spacing (ulps)
#define HALF (CAND/2)         // 1024
#define BPSEG 64              // sweep blocks per segment (NBLK/SEGP)

#define STAGE_F 512           // floats per smem stage (2KB)
#define NSTAGE 4
#define NTILE (SEGL/STAGE_F)  // 64 tiles per segment

// ---- device-resident state (no allocations allowed) ----
__device__ float g_diag[NN], g_ce[NN], g_cw[NN], g_cs[NN], g_cn[NN];
__device__ float g_r[NN], g_pa[NN], g_pb[NN], g_Ap[NN], g_t[NN];
__device__ float g_rs, g_alpha, g_beta;
__device__ double g_part[NBLK];         // per-sweep-block fp64 partials of t
__device__ double g_pref[SEGP];         // exclusive fp64 prefix per segment
__device__ float  g_seg0;               // exact chain value after segment 0
__device__ float  g_tabA[NBND][CAND];   // round-A outputs (coarse)
__device__ float  g_tabB[NBND][CAND];   // round-B outputs (fine)
__device__ float  g_centerB[NBND];      // refined centers from compose-A

// ---- monotone fp32 <-> int order mapping (total order, ulp arithmetic) ----
__device__ __forceinline__ int f2o(float f) {
    int i = __float_as_int(f);
    return i < 0 ? (int)0x80000000 - i : i;
}
__device__ __forceinline__ float o2f(int o) {
    int i = o < 0 ? (int)0x80000000 - o : o;
    return __int_as_float(i);
}

// ---- packed f32x2 helpers (per-half IEEE rn, bit-identical to scalar) ----
__device__ __forceinline__ unsigned long long pack2(uint32_t lo, uint32_t hi) {
    unsigned long long r;
    asm("mov.b64 %0, {%1, %2};" : "=l"(r) : "r"(lo), "r"(hi));
    return r;
}
__device__ __forceinline__ unsigned long long addx2(unsigned long long a,
                                                    unsigned long long b) {
    unsigned long long d;
    asm("add.rn.f32x2 %0, %1, %2;" : "=l"(d) : "l"(a), "l"(b));
    return d;
}
__device__ __forceinline__ void unpack2(unsigned long long v,
                                        float& lo, float& hi) {
    asm("mov.b64 {%0, %1}, %2;" : "=f"(lo), "=f"(hi) : "l"(v));
}

// ---- cp.async helpers ----
__device__ __forceinline__ void cp_async16(uint32_t sdst, const void* gsrc) {
    asm volatile("cp.async.cg.shared.global [%0], [%1], 16;\n" :: "r"(sdst), "l"(gsrc));
}
__device__ __forceinline__ void cp_commit() {
    asm volatile("cp.async.commit_group;\n" ::: "memory");
}
template <int N> __device__ __forceinline__ void cp_wait() {
    asm volatile("cp.async.wait_group %0;\n" :: "n"(N) : "memory");
}

// ---------------------------------------------------------------------------
// per-block fp64 partial of g_t over this block's 512 elements
// ---------------------------------------------------------------------------
__device__ __forceinline__ void block_partial(float tv) {
    __shared__ double sh[TPB];
    sh[threadIdx.x] = (double)tv;
    __syncthreads();
    for (int s = TPB / 2; s > 0; s >>= 1) {
        if (threadIdx.x < s) sh[threadIdx.x] += sh[threadIdx.x + s];
        __syncthreads();
    }
    if (threadIdx.x == 0) g_part[blockIdx.x] = sh[0];
}

// ---------------------------------------------------------------------------
// init: zero stencil planes, r = p = b, x = 0, t = rn(b*b), block partials
// ---------------------------------------------------------------------------
__global__ void init_kernel(const float* __restrict__ b, float* __restrict__ x) {
    int i = blockIdx.x * TPB + threadIdx.x;
    g_diag[i] = 0.f; g_ce[i] = 0.f; g_cw[i] = 0.f; g_cs[i] = 0.f; g_cn[i] = 0.f;
    float bv = b[i];
    g_r[i] = bv; g_pa[i] = bv; x[i] = 0.f;
    float tv = __fmul_rn(bv, bv);
    g_t[i] = tv;
    block_partial(tv);
}

__global__ void scatter_kernel(const int* __restrict__ rows,
                               const int* __restrict__ cols,
                               const float* __restrict__ vals, int nnz) {
    int k = blockIdx.x * blockDim.x + threadIdx.x;
    if (k >= nnz) return;
    int r = rows[k], c = cols[k];
    float v = vals[k];
    int d = c - r;
    if (d == 0)        g_diag[r] = v;
    else if (d == 1)   g_ce[r]   = v;
    else if (d == -1)  g_cw[r]   = v;
    else if (d == WN)  g_cs[r]   = v;
    else               g_cn[r]   = v;   // d == -WN
}

// ---------------------------------------------------------------------------
// prefix: lane s sums its segment's 64 block-partials, warp-scan -> g_pref
// ---------------------------------------------------------------------------
__global__ void prefix_kernel() {
    int lane = threadIdx.x;   // 0..31 = segment id
    double s = 0.0;
    const double* p = g_part + lane * BPSEG;
    for (int j = 0; j < BPSEG; ++j) s += p[j];
    double inc = s;
    for (int d = 1; d < 32; d <<= 1) {
        double v = __shfl_up_sync(0xFFFFFFFFu, inc, d);
        if (lane >= d) inc += v;
    }
    g_pref[lane] = inc - s;   // exclusive
}

// ---------------------------------------------------------------------------
// Segment chain, 4 candidates per lane as two interleaved f32x2 chains.
// Strict rn(acc + t_k), ascending k, per packed half — bit-identical to the
// reference's in-order scalar fp32 reduce for each candidate.
// cp.async smem staging: 4-stage 2KB ring, wait distance 2 (~3 tiles lead).
// ---------------------------------------------------------------------------
__device__ void chain_segment_x4(int seg, float s0, float s1, float s2, float s3,
                                 float* sbuf, int lane, float* out) {
    const char* gbase = (const char*)(g_t + seg * SEGL);
    uint32_t sbase = (uint32_t)__cvta_generic_to_shared(sbuf);

    unsigned long long accA = pack2(__float_as_uint(s0), __float_as_uint(s1));
    unsigned long long accB = pack2(__float_as_uint(s2), __float_as_uint(s3));

    // prologue: stages 0..NSTAGE-2 = tiles 0..2
#pragma unroll
    for (int t = 0; t < NSTAGE - 1; ++t) {
#pragma unroll
        for (int q = 0; q < 4; ++q)
            cp_async16(sbase + t * 2048 + q * 512 + lane * 16,
                       gbase + t * 2048 + q * 512 + lane * 16);
        cp_commit();
    }

    for (int t = 0; t < NTILE; ++t) {
        cp_wait<NSTAGE - 2>();
        __syncwarp();
        const uint4* s4 = (const uint4*)(sbuf + (t % NSTAGE) * STAGE_F);
#pragma unroll 8
        for (int k = 0; k < STAGE_F / 4; ++k) {
            uint4 v = s4[k];
            unsigned long long vx = pack2(v.x, v.x);
            unsigned long long vy = pack2(v.y, v.y);
            unsigned long long vz = pack2(v.z, v.z);
            unsigned long long vw = pack2(v.w, v.w);
            accA = addx2(accA, vx);  accB = addx2(accB, vx);
            accA = addx2(accA, vy);  accB = addx2(accB, vy);
            accA = addx2(accA, vz);  accB = addx2(accB, vz);
            accA = addx2(accA, vw);  accB = addx2(accB, vw);
        }
        __syncwarp();
        int ft = t + NSTAGE - 1;
        if (ft < NTILE) {
            uint32_t sdst = sbase + (ft % NSTAGE) * 2048;
            const char* gsrc = gbase + ft * 2048;
#pragma unroll
            for (int q = 0; q < 4; ++q)
                cp_async16(sdst + q * 512 + lane * 16, gsrc + q * 512 + lane * 16);
        }
        cp_commit();
    }

    unpack2(accA, out[0], out[1]);
    unpack2(accB, out[2], out[3]);
}

// ---------------------------------------------------------------------------
// Round A: coarse speculation. Block 0 = exact segment-0 chain from 0.
// Blocks 1..: boundary seg = 1..31, 4 candidates/lane at SPACE_A-ulp spacing
// around fp32(fp64 prefix), spanning +-32768 ulps.
// ---------------------------------------------------------------------------
__global__ void __launch_bounds__(32, 1) specA_kernel() {
    __shared__ __align__(16) float sbuf[NSTAGE * STAGE_F];
    int blk = blockIdx.x;
    int lane = threadIdx.x;
    float out[4];
    if (blk == 0) {
        chain_segment_x4(0, 0.0f, 0.0f, 0.0f, 0.0f, sbuf, lane, out);
        if (lane == 0) g_seg0 = out[0];
        return;
    }
    int b = blk - 1;
    int seg = 1 + b / WPB;
    int w = b % WPB;
    float center = (float)g_pref[seg];
    int co = f2o(center);
    int ci = (w * 32 + lane) * CPL;
    chain_segment_x4(seg,
                     o2f(co + (ci + 0 - HALF) * SPACE_A),
                     o2f(co + (ci + 1 - HALF) * SPACE_A),
                     o2f(co + (ci + 2 - HALF) * SPACE_A),
                     o2f(co + (ci + 3 - HALF) * SPACE_A),
                     sbuf, lane, out);
    *(float4*)&g_tabA[seg - 1][ci] = make_float4(out[0], out[1], out[2], out[3]);
}

// ---------------------------------------------------------------------------
// Compose A: nearest-candidate walk; writes refined per-boundary centers.
// ---------------------------------------------------------------------------
__global__ void composeA_kernel() {
    if (threadIdx.x != 0) return;
    float a = g_seg0;
    for (int i = 1; i < SEGP; ++i) {
        g_centerB[i - 1] = a;
        float centerA = (float)g_pref[i];
        int d = f2o(a) - f2o(centerA);
        int ci = (d + HALF * SPACE_A + SPACE_A / 2) >> 5;   // nearest, SPACE_A=32
        if (ci < 0) ci = 0;
        if (ci > CAND - 1) ci = CAND - 1;
        a = g_tabA[i - 1][ci];
    }
}

// ---------------------------------------------------------------------------
// Round B: fine speculation at 1-ulp spacing around centerB.
// ---------------------------------------------------------------------------
__global__ void __launch_bounds__(32, 1) specB_kernel() {
    __shared__ __align__(16) float sbuf[NSTAGE * STAGE_F];
    int b = blockIdx.x;
    int lane = threadIdx.x;
    int seg = 1 + b / WPB;
    int w = b % WPB;
    int co = f2o(g_centerB[seg - 1]);
    int ci = (w * 32 + lane) * CPL;
    float out[4];
    chain_segment_x4(seg,
                     o2f(co + ci + 0 - HALF),
                     o2f(co + ci + 1 - HALF),
                     o2f(co + ci + 2 - HALF),
                     o2f(co + ci + 3 - HALF),
                     sbuf, lane, out);
    *(float4*)&g_tabB[seg - 1][ci] = make_float4(out[0], out[1], out[2], out[3]);
}

// ---------------------------------------------------------------------------
// Compose B: exact bit-equality walk -> bit-identical to the serial chain.
// Serial fallback kept for the (expected-never) miss case.
// ---------------------------------------------------------------------------
__global__ void composeB_kernel(int mode) {
    if (threadIdx.x != 0) return;
    float a = g_seg0;
    bool miss = false;
    for (int i = 1; i < SEGP; ++i) {
        int d = f2o(a) - f2o(g_centerB[i - 1]);
        if (d < -HALF || d >= HALF) { miss = true; break; }
        a = g_tabB[i - 1][d + HALF];
    }
    if (miss) {
        const float4* __restrict__ t4 = (const float4*)g_t;
        float acc = 0.0f;
        for (int j = 0; j < NN / 4; j += 8) {
            float4 v0 = t4[j+0], v1 = t4[j+1], v2 = t4[j+2], v3 = t4[j+3];
            float4 v4 = t4[j+4], v5 = t4[j+5], v6 = t4[j+6], v7 = t4[j+7];
            acc=__fadd_rn(acc,v0.x); acc=__fadd_rn(acc,v0.y); acc=__fadd_rn(acc,v0.z); acc=__fadd_rn(acc,v0.w);
            acc=__fadd_rn(acc,v1.x); acc=__fadd_rn(acc,v1.y); acc=__fadd_rn(acc,v1.z); acc=__fadd_rn(acc,v1.w);
            acc=__fadd_rn(acc,v2.x); acc=__fadd_rn(acc,v2.y); acc=__fadd_rn(acc,v2.z); acc=__fadd_rn(acc,v2.w);
            acc=__fadd_rn(acc,v3.x); acc=__fadd_rn(acc,v3.y); acc=__fadd_rn(acc,v3.z); acc=__fadd_rn(acc,v3.w);
            acc=__fadd_rn(acc,v4.x); acc=__fadd_rn(acc,v4.y); acc=__fadd_rn(acc,v4.z); acc=__fadd_rn(acc,v4.w);
            acc=__fadd_rn(acc,v5.x); acc=__fadd_rn(acc,v5.y); acc=__fadd_rn(acc,v5.z); acc=__fadd_rn(acc,v5.w);
            acc=__fadd_rn(acc,v6.x); acc=__fadd_rn(acc,v6.y); acc=__fadd_rn(acc,v6.z); acc=__fadd_rn(acc,v6.w);
            acc=__fadd_rn(acc,v7.x); acc=__fadd_rn(acc,v7.y); acc=__fadd_rn(acc,v7.z); acc=__fadd_rn(acc,v7.w);
        }
        a = acc;
    }
    if (mode == 0)      { g_rs = a; g_beta = 0.0f; }
    else if (mode == 1) { g_alpha = __fdiv_rn(g_rs, a); }
    else                { g_beta = __fdiv_rn(a, g_rs); g_rs = a; }
}

// ---------------------------------------------------------------------------
// fused: p_new = r + beta*p_old ; Ap = A*p_new ; t = rn(p_new*Ap) ; partials
// Element-wise arithmetic mirrors the reference bit-for-bit (no FMA; SpMV
// adds in row-sorted COO order: E, W, S, N, diag).
// ---------------------------------------------------------------------------
__device__ __forceinline__ float pnew_at(const float* __restrict__ pin,
                                         float beta, int j) {
    return __fadd_rn(g_r[j], __fmul_rn(beta, pin[j]));
}

__global__ void spmv_kernel(int flip) {
    const float* __restrict__ pin  = flip ? g_pb : g_pa;
    float*       __restrict__ pout = flip ? g_pa : g_pb;

    int i = blockIdx.x * TPB + threadIdx.x;
    float beta = g_beta;
    int xc = i & (WN - 1);

    float pn = pnew_at(pin, beta, i);

    float acc = 0.0f;
    if (xc < WN - 1) acc = __fadd_rn(acc, __fmul_rn(g_ce[i], pnew_at(pin, beta, i + 1)));
    if (xc > 0)      acc = __fadd_rn(acc, __fmul_rn(g_cw[i], pnew_at(pin, beta, i - 1)));
    if (i < NN - WN) acc = __fadd_rn(acc, __fmul_rn(g_cs[i], pnew_at(pin, beta, i + WN)));
    if (i >= WN)     acc = __fadd_rn(acc, __fmul_rn(g_cn[i], pnew_at(pin, beta, i - WN)));
    acc = __fadd_rn(acc, __fmul_rn(g_diag[i], pn));

    pout[i] = pn;
    g_Ap[i] = acc;
    float tv = __fmul_rn(pn, acc);
    g_t[i] = tv;
    block_partial(tv);
}

// ---------------------------------------------------------------------------
// fused: x += alpha*p ; r -= alpha*Ap ; t = rn(r*r) ; partials  (no FMA)
// ---------------------------------------------------------------------------
__global__ void update_kernel(float* __restrict__ x, int flip) {
    const float* __restrict__ p = flip ? g_pa : g_pb;

    int i = blockIdx.x * TPB + threadIdx.x;
    float alpha = g_alpha;
    x[i] = __fadd_rn(x[i], __fmul_rn(alpha, p[i]));
    float rv = __fsub_rn(g_r[i], __fmul_rn(alpha, g_Ap[i]));
    g_r[i] = rv;
    float tv = __fmul_rn(rv, rv);
    g_t[i] = tv;
    block_partial(tv);
}

// ---------------------------------------------------------------------------
static inline void launch_dot(int mode) {
    prefix_kernel<<<1, 32>>>();
    specA_kernel<<<1 + NBND * WPB, 32>>>();
    composeA_kernel<<<1, 32>>>();
    specB_kernel<<<NBND * WPB, 32>>>();
    composeB_kernel<<<1, 32>>>(mode);
}

extern "C" void kernel_launch(void* const* d_in, const int* in_sizes, int n_in,
                              void* d_out, int out_size) {
    const int*   rows = (const int*)d_in[0];
    const int*   cols = (const int*)d_in[1];
    const float* vals = (const float*)d_in[2];
    const float* b    = (const float*)d_in[3];
    float*       x    = (float*)d_out;
    int nnz = in_sizes[0];

    init_kernel<<<NBLK, TPB>>>(b, x);
    scatter_kernel<<<(nnz + 255) / 256, 256>>>(rows, cols, vals, nnz);
    launch_dot(0);

    for (int it = 0; it < STEPS; ++it) {
        int flip = it & 1;
        spmv_kernel<<<NBLK, TPB>>>(flip);
        launch_dot(1);
        update_kernel<<<NBLK, TPB>>>(x, flip);
        launch_dot(2);
    }
}

// round 17
// speedup vs baseline: 25.4122x; 1.0723x over previous
#include <cuda_runtime.h>
#include <cstdint>

#define HN 1024
#define WN 1024
#define NN (HN*WN)
#define TPB 512
#define NBLK (NN/TPB)   // 2048
#define STEPS 50

#define SEGP 64
#define SEGL (NN/SEGP)        // 16384 elements per segment
#define NBND (SEGP-1)         // 63 boundaries
#define CAND 2048             // candidates per boundary (both rounds)
#define CPL  4                // candidates per lane (2 x f32x2 chains)
#define WPB  (CAND/(32*CPL))  // 16 warps per boundary
#define SPACE_A 32            // round-A candidate spacing (ulps)
#define HALF (CAND/2)         // 1024
#define BPSEG (NBLK/SEGP)     // 32 sweep blocks per segment

#define STAGE_F 512           // floats per smem stage (2KB)
#define NSTAGE 4
#define NTILE (SEGL/STAGE_F)  // 32 tiles per segment

// ---- device-resident state (no allocations allowed) ----
__device__ float g_diag[NN], g_ce[NN], g_cw[NN], g_cs[NN], g_cn[NN];
__device__ float g_r[NN], g_pa[NN], g_pb[NN], g_Ap[NN], g_t[NN];
__device__ float g_rs, g_alpha, g_beta;
__device__ double g_part[NBLK];         // per-sweep-block fp64 partials of t
__device__ double g_pref[SEGP];         // fp64 exclusive prefix (by specA)
__device__ float  g_seg0;               // exact chain value after segment 0
__device__ float  g_tabA[NBND][CAND];   // round-A outputs (coarse)
__device__ float  g_tabB[NBND][CAND];   // round-B outputs (fine)
__device__ float  g_centerB[NBND];      // refined centers from compose-A

// ---- monotone fp32 <-> int order mapping (total order, ulp arithmetic) ----
__device__ __forceinline__ int f2o(float f) {
    int i = __float_as_int(f);
    return i < 0 ? (int)0x80000000 - i : i;
}
__device__ __forceinline__ float o2f(int o) {
    int i = o < 0 ? (int)0x80000000 - o : o;
    return __int_as_float(i);
}

// ---- packed f32x2 helpers (per-half IEEE rn, bit-identical to scalar) ----
__device__ __forceinline__ unsigned long long pack2(uint32_t lo, uint32_t hi) {
    unsigned long long r;
    asm("mov.b64 %0, {%1, %2};" : "=l"(r) : "r"(lo), "r"(hi));
    return r;
}
__device__ __forceinline__ unsigned long long addx2(unsigned long long a,
                                                    unsigned long long b) {
    unsigned long long d;
    asm("add.rn.f32x2 %0, %1, %2;" : "=l"(d) : "l"(a), "l"(b));
    return d;
}
__device__ __forceinline__ void unpack2(unsigned long long v,
                                        float& lo, float& hi) {
    asm("mov.b64 {%0, %1}, %2;" : "=f"(lo), "=f"(hi) : "l"(v));
}

// ---- cp.async helpers ----
__device__ __forceinline__ void cp_async16(uint32_t sdst, const void* gsrc) {
    asm volatile("cp.async.cg.shared.global [%0], [%1], 16;\n" :: "r"(sdst), "l"(gsrc));
}
__device__ __forceinline__ void cp_commit() {
    asm volatile("cp.async.commit_group;\n" ::: "memory");
}
template <int N> __device__ __forceinline__ void cp_wait() {
    asm volatile("cp.async.wait_group %0;\n" :: "n"(N) : "memory");
}

// ---------------------------------------------------------------------------
// per-block fp64 partial of g_t over this block's 512 elements
// ---------------------------------------------------------------------------
__device__ __forceinline__ void block_partial(float tv) {
    __shared__ double sh[TPB];
    sh[threadIdx.x] = (double)tv;
    __syncthreads();
    for (int s = TPB / 2; s > 0; s >>= 1) {
        if (threadIdx.x < s) sh[threadIdx.x] += sh[threadIdx.x + s];
        __syncthreads();
    }
    if (threadIdx.x == 0) g_part[blockIdx.x] = sh[0];
}

// ---------------------------------------------------------------------------
// init: zero stencil planes, r = p = b, x = 0, t = rn(b*b), block partials
// ---------------------------------------------------------------------------
__global__ void init_kernel(const float* __restrict__ b, float* __restrict__ x) {
    int i = blockIdx.x * TPB + threadIdx.x;
    g_diag[i] = 0.f; g_ce[i] = 0.f; g_cw[i] = 0.f; g_cs[i] = 0.f; g_cn[i] = 0.f;
    float bv = b[i];
    g_r[i] = bv; g_pa[i] = bv; x[i] = 0.f;
    float tv = __fmul_rn(bv, bv);
    g_t[i] = tv;
    block_partial(tv);
}

__global__ void scatter_kernel(const int* __restrict__ rows,
                               const int* __restrict__ cols,
                               const float* __restrict__ vals, int nnz) {
    int k = blockIdx.x * blockDim.x + threadIdx.x;
    if (k >= nnz) return;
    int r = rows[k], c = cols[k];
    float v = vals[k];
    int d = c - r;
    if (d == 0)        g_diag[r] = v;
    else if (d == 1)   g_ce[r]   = v;
    else if (d == -1)  g_cw[r]   = v;
    else if (d == WN)  g_cs[r]   = v;
    else               g_cn[r]   = v;   // d == -WN
}

// ---------------------------------------------------------------------------
// Segment chain, 4 candidates per lane as two interleaved f32x2 chains.
// Strict rn(acc + t_k), ascending k, per packed half — bit-identical to the
// reference's in-order scalar fp32 reduce for each candidate.
// cp.async smem staging: 4-stage 2KB ring, wait distance 2 (~3 tiles lead).
// ---------------------------------------------------------------------------
__device__ void chain_segment_x4(int seg, float s0, float s1, float s2, float s3,
                                 float* sbuf, int lane, float* out) {
    const char* gbase = (const char*)(g_t + seg * SEGL);
    uint32_t sbase = (uint32_t)__cvta_generic_to_shared(sbuf);

    unsigned long long accA = pack2(__float_as_uint(s0), __float_as_uint(s1));
    unsigned long long accB = pack2(__float_as_uint(s2), __float_as_uint(s3));

    // prologue: stages 0..NSTAGE-2 = tiles 0..2
#pragma unroll
    for (int t = 0; t < NSTAGE - 1; ++t) {
#pragma unroll
        for (int q = 0; q < 4; ++q)
            cp_async16(sbase + t * 2048 + q * 512 + lane * 16,
                       gbase + t * 2048 + q * 512 + lane * 16);
        cp_commit();
    }

    for (int t = 0; t < NTILE; ++t) {
        cp_wait<NSTAGE - 2>();
        __syncwarp();
        const uint4* s4 = (const uint4*)(sbuf + (t % NSTAGE) * STAGE_F);
#pragma unroll 8
        for (int k = 0; k < STAGE_F / 4; ++k) {
            uint4 v = s4[k];
            unsigned long long vx = pack2(v.x, v.x);
            unsigned long long vy = pack2(v.y, v.y);
            unsigned long long vz = pack2(v.z, v.z);
            unsigned long long vw = pack2(v.w, v.w);
            accA = addx2(accA, vx);  accB = addx2(accB, vx);
            accA = addx2(accA, vy);  accB = addx2(accB, vy);
            accA = addx2(accA, vz);  accB = addx2(accB, vz);
            accA = addx2(accA, vw);  accB = addx2(accB, vw);
        }
        __syncwarp();
        int ft = t + NSTAGE - 1;
        if (ft < NTILE) {
            uint32_t sdst = sbase + (ft % NSTAGE) * 2048;
            const char* gsrc = gbase + ft * 2048;
#pragma unroll
            for (int q = 0; q < 4; ++q)
                cp_async16(sdst + q * 512 + lane * 16, gsrc + q * 512 + lane * 16);
        }
        cp_commit();
    }

    unpack2(accA, out[0], out[1]);
    unpack2(accB, out[2], out[3]);
}

// ---------------------------------------------------------------------------
// Round A: coarse speculation + inline fp64 prefix. Block 0 = exact segment-0
// chain from 0. Blocks 1..: boundary seg = 1..63; every block of a boundary
// computes the same deterministic fp64 prefix (lane-strided + xor-shuffle
// reduce over g_part[0 .. seg*BPSEG)); candidates at SPACE_A-ulp spacing
// around fp32(prefix), spanning +-32768 ulps.
// ---------------------------------------------------------------------------
__global__ void __launch_bounds__(32, 1) specA_kernel() {
    __shared__ __align__(16) float sbuf[NSTAGE * STAGE_F];
    int blk = blockIdx.x;
    int lane = threadIdx.x;
    float out[4];
    if (blk == 0) {
        chain_segment_x4(0, 0.0f, 0.0f, 0.0f, 0.0f, sbuf, lane, out);
        if (lane == 0) g_seg0 = out[0];
        return;
    }
    int b = blk - 1;
    int seg = 1 + b / WPB;
    int w = b % WPB;

    // deterministic fp64 prefix: identical across all blocks of this boundary
    double s = 0.0;
    int cnt = seg * BPSEG;
    for (int j = lane; j < cnt; j += 32) s += g_part[j];
#pragma unroll
    for (int d = 16; d > 0; d >>= 1) s += __shfl_xor_sync(0xFFFFFFFFu, s, d);
    if (w == 0 && lane == 0) g_pref[seg] = s;   // publish for composeA

    float center = (float)s;
    int co = f2o(center);
    int ci = (w * 32 + lane) * CPL;
    chain_segment_x4(seg,
                     o2f(co + (ci + 0 - HALF) * SPACE_A),
                     o2f(co + (ci + 1 - HALF) * SPACE_A),
                     o2f(co + (ci + 2 - HALF) * SPACE_A),
                     o2f(co + (ci + 3 - HALF) * SPACE_A),
                     sbuf, lane, out);
    *(float4*)&g_tabA[seg - 1][ci] = make_float4(out[0], out[1], out[2], out[3]);
}

// ---------------------------------------------------------------------------
// Compose A: nearest-candidate walk; writes refined per-boundary centers.
// ---------------------------------------------------------------------------
__global__ void composeA_kernel() {
    if (threadIdx.x != 0) return;
    float a = g_seg0;
    for (int i = 1; i < SEGP; ++i) {
        g_centerB[i - 1] = a;
        float centerA = (float)g_pref[i];
        int d = f2o(a) - f2o(centerA);
        int ci = (d + HALF * SPACE_A + SPACE_A / 2) >> 5;   // nearest, SPACE_A=32
        if (ci < 0) ci = 0;
        if (ci > CAND - 1) ci = CAND - 1;
        a = g_tabA[i - 1][ci];
    }
}

// ---------------------------------------------------------------------------
// Round B: fine speculation at 1-ulp spacing around centerB.
// ---------------------------------------------------------------------------
__global__ void __launch_bounds__(32, 1) specB_kernel() {
    __shared__ __align__(16) float sbuf[NSTAGE * STAGE_F];
    int b = blockIdx.x;
    int lane = threadIdx.x;
    int seg = 1 + b / WPB;
    int w = b % WPB;
    int co = f2o(g_centerB[seg - 1]);
    int ci = (w * 32 + lane) * CPL;
    float out[4];
    chain_segment_x4(seg,
                     o2f(co + ci + 0 - HALF),
                     o2f(co + ci + 1 - HALF),
                     o2f(co + ci + 2 - HALF),
                     o2f(co + ci + 3 - HALF),
                     sbuf, lane, out);
    *(float4*)&g_tabB[seg - 1][ci] = make_float4(out[0], out[1], out[2], out[3]);
}

// ---------------------------------------------------------------------------
// Compose B: exact bit-equality walk -> bit-identical to the serial chain.
// Serial fallback kept for the (expected-never) miss case.
// ---------------------------------------------------------------------------
__global__ void composeB_kernel(int mode) {
    if (threadIdx.x != 0) return;
    float a = g_seg0;
    bool miss = false;
    for (int i = 1; i < SEGP; ++i) {
        int d = f2o(a) - f2o(g_centerB[i - 1]);
        if (d < -HALF || d >= HALF) { miss = true; break; }
        a = g_tabB[i - 1][d + HALF];
    }
    if (miss) {
        const float4* __restrict__ t4 = (const float4*)g_t;
        float acc = 0.0f;
        for (int j = 0; j < NN / 4; j += 8) {
            float4 v0 = t4[j+0], v1 = t4[j+1], v2 = t4[j+2], v3 = t4[j+3];
            float4 v4 = t4[j+4], v5 = t4[j+5], v6 = t4[j+6], v7 = t4[j+7];
            acc=__fadd_rn(acc,v0.x); acc=__fadd_rn(acc,v0.y); acc=__fadd_rn(acc,v0.z); acc=__fadd_rn(acc,v0.w);
            acc=__fadd_rn(acc,v1.x); acc=__fadd_rn(acc,v1.y); acc=__fadd_rn(acc,v1.z); acc=__fadd_rn(acc,v1.w);
            acc=__fadd_rn(acc,v2.x); acc=__fadd_rn(acc,v2.y); acc=__fadd_rn(acc,v2.z); acc=__fadd_rn(acc,v2.w);
            acc=__fadd_rn(acc,v3.x); acc=__fadd_rn(acc,v3.y); acc=__fadd_rn(acc,v3.z); acc=__fadd_rn(acc,v3.w);
            acc=__fadd_rn(acc,v4.x); acc=__fadd_rn(acc,v4.y); acc=__fadd_rn(acc,v4.z); acc=__fadd_rn(acc,v4.w);
            acc=__fadd_rn(acc,v5.x); acc=__fadd_rn(acc,v5.y); acc=__fadd_rn(acc,v5.z); acc=__fadd_rn(acc,v5.w);
            acc=__fadd_rn(acc,v6.x); acc=__fadd_rn(acc,v6.y); acc=__fadd_rn(acc,v6.z); acc=__fadd_rn(acc,v6.w);
            acc=__fadd_rn(acc,v7.x); acc=__fadd_rn(acc,v7.y); acc=__fadd_rn(acc,v7.z); acc=__fadd_rn(acc,v7.w);
        }
        a = acc;
    }
    if (mode == 0)      { g_rs = a; g_beta = 0.0f; }
    else if (mode == 1) { g_alpha = __fdiv_rn(g_rs, a); }
    else                { g_beta = __fdiv_rn(a, g_rs); g_rs = a; }
}

// ---------------------------------------------------------------------------
// fused: p_new = r + beta*p_old ; Ap = A*p_new ; t = rn(p_new*Ap) ; partials
// Element-wise arithmetic mirrors the reference bit-for-bit (no FMA; SpMV
// adds in row-sorted COO order: E, W, S, N, diag).
// ---------------------------------------------------------------------------
__device__ __forceinline__ float pnew_at(const float* __restrict__ pin,
                                         float beta, int j) {
    return __fadd_rn(g_r[j], __fmul_rn(beta, pin[j]));
}

__global__ void spmv_kernel(int flip) {
    const float* __restrict__ pin  = flip ? g_pb : g_pa;
    float*       __restrict__ pout = flip ? g_pa : g_pb;

    int i = blockIdx.x * TPB + threadIdx.x;
    float beta = g_beta;
    int xc = i & (WN - 1);

    float pn = pnew_at(pin, beta, i);

    float acc = 0.0f;
    if (xc < WN - 1) acc = __fadd_rn(acc, __fmul_rn(g_ce[i], pnew_at(pin, beta, i + 1)));
    if (xc > 0)      acc = __fadd_rn(acc, __fmul_rn(g_cw[i], pnew_at(pin, beta, i - 1)));
    if (i < NN - WN) acc = __fadd_rn(acc, __fmul_rn(g_cs[i], pnew_at(pin, beta, i + WN)));
    if (i >= WN)     acc = __fadd_rn(acc, __fmul_rn(g_cn[i], pnew_at(pin, beta, i - WN)));
    acc = __fadd_rn(acc, __fmul_rn(g_diag[i], pn));

    pout[i] = pn;
    g_Ap[i] = acc;
    float tv = __fmul_rn(pn, acc);
    g_t[i] = tv;
    block_partial(tv);
}

// ---------------------------------------------------------------------------
// fused: x += alpha*p ; r -= alpha*Ap ; t = rn(r*r) ; partials  (no FMA)
// ---------------------------------------------------------------------------
__global__ void update_kernel(float* __restrict__ x, int flip) {
    const float* __restrict__ p = flip ? g_pa : g_pb;

    int i = blockIdx.x * TPB + threadIdx.x;
    float alpha = g_alpha;
    x[i] = __fadd_rn(x[i], __fmul_rn(alpha, p[i]));
    float rv = __fsub_rn(g_r[i], __fmul_rn(alpha, g_Ap[i]));
    g_r[i] = rv;
    float tv = __fmul_rn(rv, rv);
    g_t[i] = tv;
    block_partial(tv);
}

// ---------------------------------------------------------------------------
static inline void launch_dot(int mode) {
    specA_kernel<<<1 + NBND * WPB, 32>>>();
    composeA_kernel<<<1, 32>>>();
    specB_kernel<<<NBND * WPB, 32>>>();
    composeB_kernel<<<1, 32>>>(mode);
}

extern "C" void kernel_launch(void* const* d_in, const int* in_sizes, int n_in,
                              void* d_out, int out_size) {
    const int*   rows = (const int*)d_in[0];
    const int*   cols = (const int*)d_in[1];
    const float* vals = (const float*)d_in[2];
    const float* b    = (const float*)d_in[3];
    float*       x    = (float*)d_out;
    int nnz = in_sizes[0];

    init_kernel<<<NBLK, TPB>>>(b, x);
    scatter_kernel<<<(nnz + 255) / 256, 256>>>(rows, cols, vals, nnz);
    launch_dot(0);

    for (int it = 0; it < STEPS; ++it) {
        int flip = it & 1;
        spmv_kernel<<<NBLK, TPB>>>(flip);
        launch_dot(1);
        update_kernel<<<NBLK, TPB>>>(x, flip);
        if (it < STEPS - 1) launch_dot(2);   // final beta is never consumed
    }
}